// round 2
// baseline (speedup 1.0000x reference)
#include <cuda_runtime.h>
#include <cuda_fp16.h>
#include <cstdint>

#define NNODES 100000
#define NEDGES 1600000
#define NF4    (NNODES * 16)        // float4 slots per fp32 feature plane (64 floats/row)

// ---------------------------------------------------------------------------
// Device-global scratch (no allocations allowed).
// feat planes 0..4 in fp16: 5 * 100000*64*2 B = 64 MB
__device__ __half2 g_feat[5][NNODES * 32];
__device__ float4  g_agg4[NF4];          // fp32 accumulator, 25.6 MB
__device__ int2    g_edges[NEDGES];      // packed (src,dst), 12.8 MB
__device__ float   g_deg[NNODES];
__device__ float   g_dis[NNODES];
__device__ int     g_idx64;

// ---------------------------------------------------------------------------
// Detect index width: int64 nonneg values => every odd 32-bit word is zero.
__global__ void detect_idx_kernel(const int* __restrict__ ei32) {
    int lane = threadIdx.x;
    int nz = 0;
    for (int i = lane; i < 2048; i += 32) nz |= ei32[2 * i + 1];
    unsigned m = __ballot_sync(0xffffffffu, nz != 0);
    if (lane == 0) g_idx64 = (m == 0) ? 1 : 0;
}

// ---------------------------------------------------------------------------
// init: feat0 = half(x), agg = 0, deg = 0
__global__ void init_kernel(const float4* __restrict__ x4) {
    int i = blockIdx.x * blockDim.x + threadIdx.x;
    if (i >= NF4) return;
    float4 v = x4[i];
    g_feat[0][2 * i]     = __floats2half2_rn(v.x, v.y);
    g_feat[0][2 * i + 1] = __floats2half2_rn(v.z, v.w);
    g_agg4[i] = make_float4(0.f, 0.f, 0.f, 0.f);
    if (i < NNODES) g_deg[i] = 0.f;
}

// ---------------------------------------------------------------------------
// prep: pack edges to int2 + accumulate in-degree (dst row)
__global__ void prep_kernel(const void* __restrict__ eiv) {
    int e = blockIdx.x * blockDim.x + threadIdx.x;
    if (e >= NEDGES) return;
    int s, d;
    if (g_idx64) {
        const long long* p = (const long long*)eiv;
        s = (int)p[e];
        d = (int)p[NEDGES + e];
    } else {
        const int* p = (const int*)eiv;
        s = p[e];
        d = p[NEDGES + e];
    }
    g_edges[e] = make_int2(s, d);
    atomicAdd(&g_deg[d], 1.0f);
}

__global__ void dis_kernel() {
    int i = blockIdx.x * blockDim.x + threadIdx.x;
    if (i >= NNODES) return;
    g_dis[i] = rsqrtf(fmaxf(g_deg[i], 1.0f));
}

// ---------------------------------------------------------------------------
// scatter iteration k: agg[dst] += dis[src] * feat_{k-1}[src]
// 8 lanes per edge: each lane loads 16 B (8 halves), issues 2x red.v4.f32.
__global__ void scatter_kernel(int k) {
    int t = blockIdx.x * blockDim.x + threadIdx.x;
    int e = t >> 3;
    if (e >= NEDGES) return;
    int lane = t & 7;

    int2 ed = __ldg(&g_edges[e]);
    float w = __ldg(&g_dis[ed.x]);

    const uint4* fp = reinterpret_cast<const uint4*>(g_feat[k - 1]);
    uint4 raw = __ldg(&fp[ed.x * 8 + lane]);

    __half2 h0 = *reinterpret_cast<__half2*>(&raw.x);
    __half2 h1 = *reinterpret_cast<__half2*>(&raw.y);
    __half2 h2 = *reinterpret_cast<__half2*>(&raw.z);
    __half2 h3 = *reinterpret_cast<__half2*>(&raw.w);
    float2 f0 = __half22float2(h0);
    float2 f1 = __half22float2(h1);
    float2 f2 = __half22float2(h2);
    float2 f3 = __half22float2(h3);

    float4* p0 = &g_agg4[ed.y * 16 + lane * 2];
    unsigned long long gp0, gp1;
    asm("cvta.to.global.u64 %0, %1;" : "=l"(gp0) : "l"(p0));
    asm("cvta.to.global.u64 %0, %1;" : "=l"(gp1) : "l"(p0 + 1));
    asm volatile("red.global.add.v4.f32 [%0], {%1, %2, %3, %4};"
                 :: "l"(gp0), "f"(w * f0.x), "f"(w * f0.y),
                    "f"(w * f1.x), "f"(w * f1.y) : "memory");
    asm volatile("red.global.add.v4.f32 [%0], {%1, %2, %3, %4};"
                 :: "l"(gp1), "f"(w * f2.x), "f"(w * f2.y),
                    "f"(w * f3.x), "f"(w * f3.y) : "memory");
}

// ---------------------------------------------------------------------------
// update iteration k: feat_k = feat_{k-1} - dis[n] * agg ; agg = 0 (if more iters)
__global__ void update_kernel(int k, int zero_agg) {
    int i = blockIdx.x * blockDim.x + threadIdx.x;
    if (i >= NF4) return;
    int node = i >> 4;
    float dis = g_dis[node];

    float4 a = g_agg4[i];
    float2 f0 = __half22float2(g_feat[k - 1][2 * i]);
    float2 f1 = __half22float2(g_feat[k - 1][2 * i + 1]);

    g_feat[k][2 * i]     = __floats2half2_rn(f0.x - dis * a.x, f0.y - dis * a.y);
    g_feat[k][2 * i + 1] = __floats2half2_rn(f1.x - dis * a.z, f1.y - dis * a.w);

    if (zero_agg) g_agg4[i] = make_float4(0.f, 0.f, 0.f, 0.f);
}

// ---------------------------------------------------------------------------
// final: out = th0*x + th1*f1 + th2*f2 + th3*f3 + th4*f4
__global__ void final_kernel(const float4* __restrict__ x4,
                             float4* __restrict__ out4) {
    int i = blockIdx.x * blockDim.x + threadIdx.x;
    if (i >= NF4) return;
    float4 v = x4[i];
    float4 o;
    o.x = 0.6f * v.x; o.y = 0.6f * v.y; o.z = 0.6f * v.z; o.w = 0.6f * v.w;

    const float TH[5] = {0.6f, -0.4f, 0.3f, -0.2f, 0.1f};
#pragma unroll
    for (int k = 1; k <= 4; k++) {
        float2 f0 = __half22float2(g_feat[k][2 * i]);
        float2 f1 = __half22float2(g_feat[k][2 * i + 1]);
        o.x += TH[k] * f0.x;
        o.y += TH[k] * f0.y;
        o.z += TH[k] * f1.x;
        o.w += TH[k] * f1.y;
    }
    out4[i] = o;
}

// ---------------------------------------------------------------------------
extern "C" void kernel_launch(void* const* d_in, const int* in_sizes, int n_in,
                              void* d_out, int out_size) {
    const float4* x4 = (const float4*)d_in[0];
    const void*   ei = d_in[1];
    float4* out4 = (float4*)d_out;

    detect_idx_kernel<<<1, 32>>>((const int*)ei);
    init_kernel<<<(NF4 + 255) / 256, 256>>>(x4);
    prep_kernel<<<(NEDGES + 255) / 256, 256>>>(ei);
    dis_kernel<<<(NNODES + 255) / 256, 256>>>();

    const int scatter_threads = NEDGES * 8;
    for (int k = 1; k <= 4; k++) {
        scatter_kernel<<<(scatter_threads + 255) / 256, 256>>>(k);
        update_kernel<<<(NF4 + 255) / 256, 256>>>(k, (k < 4) ? 1 : 0);
    }
    final_kernel<<<(NF4 + 255) / 256, 256>>>(x4, out4);
}

// round 3
// speedup vs baseline: 2.6801x; 2.6801x over previous
#include <cuda_runtime.h>
#include <cuda_fp16.h>
#include <cstdint>

#define NNODES 100000
#define NEDGES 1600000
#define NB     391            // ceil(NNODES/256)
#define NF4    (NNODES * 16)  // float4 slots per fp32 plane

// ---------------------------------------------------------------------------
// Device-global scratch (no allocation allowed).
__device__ __half2 g_feat[5][NNODES * 32];   // 5 fp16 planes, 12.8 MB each
__device__ int2    g_csr[NEDGES];            // {src, bits(dis[src])} sorted by dst
__device__ int     g_off[NNODES + 1];
__device__ int     g_cursor[NNODES];
__device__ int     g_deg[NNODES];
__device__ float   g_dis[NNODES];
__device__ int     g_blocksum[512];
__device__ int     g_blockoff[512];
__device__ int     g_idx64;

// ---------------------------------------------------------------------------
__global__ void detect_idx_kernel(const int* __restrict__ ei32) {
    int lane = threadIdx.x;
    int nz = 0;
    for (int i = lane; i < 2048; i += 32) nz |= ei32[2 * i + 1];
    unsigned m = __ballot_sync(0xffffffffu, nz != 0);
    if (lane == 0) g_idx64 = (m == 0) ? 1 : 0;
}

__global__ void deg_kernel(const void* __restrict__ eiv) {
    int e = blockIdx.x * blockDim.x + threadIdx.x;
    if (e >= NEDGES) return;
    int d;
    if (g_idx64) d = (int)((const long long*)eiv)[NEDGES + e];
    else         d = ((const int*)eiv)[NEDGES + e];
    atomicAdd(&g_deg[d], 1);
}

// zero deg (d_out is poisoned, device globals zero-init at load but NOT
// between graph replays -> must reset every launch)
__global__ void zerodeg_kernel() {
    int i = blockIdx.x * blockDim.x + threadIdx.x;
    if (i < NNODES) g_deg[i] = 0;
}

// ---------------------------------------------------------------------------
// 3-kernel exclusive scan of g_deg -> g_off / g_cursor
__global__ void partial_kernel() {
    __shared__ int s[256];
    int i = blockIdx.x * 256 + threadIdx.x;
    int v = (i < NNODES) ? g_deg[i] : 0;
    s[threadIdx.x] = v; __syncthreads();
    for (int st = 128; st > 0; st >>= 1) {
        if (threadIdx.x < st) s[threadIdx.x] += s[threadIdx.x + st];
        __syncthreads();
    }
    if (threadIdx.x == 0) g_blocksum[blockIdx.x] = s[0];
}

__global__ void scanblock_kernel() {
    __shared__ int s[512];
    int t = threadIdx.x;
    int v = (t < NB) ? g_blocksum[t] : 0;
    s[t] = v; __syncthreads();
    for (int st = 1; st < 512; st <<= 1) {
        int add = (t >= st) ? s[t - st] : 0;
        __syncthreads();
        s[t] += add;
        __syncthreads();
    }
    if (t < NB) g_blockoff[t] = s[t] - v;   // exclusive
}

__global__ void offsets_kernel() {
    __shared__ int s[256];
    int i = blockIdx.x * 256 + threadIdx.x;
    int v = (i < NNODES) ? g_deg[i] : 0;
    s[threadIdx.x] = v; __syncthreads();
    for (int st = 1; st < 256; st <<= 1) {
        int add = (threadIdx.x >= st) ? s[threadIdx.x - st] : 0;
        __syncthreads();
        s[threadIdx.x] += add;
        __syncthreads();
    }
    int off = g_blockoff[blockIdx.x] + s[threadIdx.x] - v;  // exclusive
    if (i < NNODES) { g_off[i] = off; g_cursor[i] = off; }
    if (i == NNODES - 1) g_off[NNODES] = off + v;
}

__global__ void dis_kernel() {
    int i = blockIdx.x * blockDim.x + threadIdx.x;
    if (i >= NNODES) return;
    g_dis[i] = rsqrtf(fmaxf((float)g_deg[i], 1.0f));
}

// fill CSR: pos = cursor[dst]++ ; csr[pos] = {src, bits(dis[src])}
__global__ void fill_kernel(const void* __restrict__ eiv) {
    int e = blockIdx.x * blockDim.x + threadIdx.x;
    if (e >= NEDGES) return;
    int s, d;
    if (g_idx64) {
        const long long* p = (const long long*)eiv;
        s = (int)p[e]; d = (int)p[NEDGES + e];
    } else {
        const int* p = (const int*)eiv;
        s = p[e]; d = p[NEDGES + e];
    }
    int pos = atomicAdd(&g_cursor[d], 1);
    g_csr[pos] = make_int2(s, __float_as_int(g_dis[s]));
}

// ---------------------------------------------------------------------------
__global__ void init_kernel(const float4* __restrict__ x4) {
    int i = blockIdx.x * blockDim.x + threadIdx.x;
    if (i >= NF4) return;
    float4 v = x4[i];
    g_feat[0][2 * i]     = __floats2half2_rn(v.x, v.y);
    g_feat[0][2 * i + 1] = __floats2half2_rn(v.z, v.w);
}

// ---------------------------------------------------------------------------
// Pull-mode fused iteration: feat_k[n] = feat_{k-1}[n] - dis[n] * sum_{s in N(n)} dis[s]*feat_{k-1}[s]
// 8 lanes per node; lane owns 16 B (8 halves) of the 128 B row; fp32 accum.
__device__ __forceinline__ void acc_row(float2& a0, float2& a1, float2& a2, float2& a3,
                                        float w, uint4 r) {
    float2 f0 = __half22float2(*reinterpret_cast<__half2*>(&r.x));
    float2 f1 = __half22float2(*reinterpret_cast<__half2*>(&r.y));
    float2 f2 = __half22float2(*reinterpret_cast<__half2*>(&r.z));
    float2 f3 = __half22float2(*reinterpret_cast<__half2*>(&r.w));
    a0.x = fmaf(w, f0.x, a0.x); a0.y = fmaf(w, f0.y, a0.y);
    a1.x = fmaf(w, f1.x, a1.x); a1.y = fmaf(w, f1.y, a1.y);
    a2.x = fmaf(w, f2.x, a2.x); a2.y = fmaf(w, f2.y, a2.y);
    a3.x = fmaf(w, f3.x, a3.x); a3.y = fmaf(w, f3.y, a3.y);
}

__global__ void gather_kernel(int k) {
    int t = blockIdx.x * blockDim.x + threadIdx.x;
    int node = t >> 3;
    if (node >= NNODES) return;
    int sl = t & 7;

    const uint4* fp = reinterpret_cast<const uint4*>(g_feat[k - 1]);
    uint4*       fn = reinterpret_cast<uint4*>(g_feat[k]);

    int beg = g_off[node], end = g_off[node + 1];

    float2 a0 = {0.f, 0.f}, a1 = {0.f, 0.f}, a2 = {0.f, 0.f}, a3 = {0.f, 0.f};

    int j = beg;
    // 4-wide unroll for MLP
    for (; j + 4 <= end; j += 4) {
        int2 e0 = g_csr[j];
        int2 e1 = g_csr[j + 1];
        int2 e2 = g_csr[j + 2];
        int2 e3 = g_csr[j + 3];
        uint4 r0 = __ldg(&fp[e0.x * 8 + sl]);
        uint4 r1 = __ldg(&fp[e1.x * 8 + sl]);
        uint4 r2 = __ldg(&fp[e2.x * 8 + sl]);
        uint4 r3 = __ldg(&fp[e3.x * 8 + sl]);
        acc_row(a0, a1, a2, a3, __int_as_float(e0.y), r0);
        acc_row(a0, a1, a2, a3, __int_as_float(e1.y), r1);
        acc_row(a0, a1, a2, a3, __int_as_float(e2.y), r2);
        acc_row(a0, a1, a2, a3, __int_as_float(e3.y), r3);
    }
    for (; j < end; j++) {
        int2 e0 = g_csr[j];
        uint4 r0 = __ldg(&fp[e0.x * 8 + sl]);
        acc_row(a0, a1, a2, a3, __int_as_float(e0.y), r0);
    }

    float disn = g_dis[node];
    uint4 own = fp[node * 8 + sl];
    float2 f0 = __half22float2(*reinterpret_cast<__half2*>(&own.x));
    float2 f1 = __half22float2(*reinterpret_cast<__half2*>(&own.y));
    float2 f2 = __half22float2(*reinterpret_cast<__half2*>(&own.z));
    float2 f3 = __half22float2(*reinterpret_cast<__half2*>(&own.w));

    __half2 o0 = __floats2half2_rn(f0.x - disn * a0.x, f0.y - disn * a0.y);
    __half2 o1 = __floats2half2_rn(f1.x - disn * a1.x, f1.y - disn * a1.y);
    __half2 o2 = __floats2half2_rn(f2.x - disn * a2.x, f2.y - disn * a2.y);
    __half2 o3 = __floats2half2_rn(f3.x - disn * a3.x, f3.y - disn * a3.y);

    uint4 out;
    out.x = *reinterpret_cast<unsigned*>(&o0);
    out.y = *reinterpret_cast<unsigned*>(&o1);
    out.z = *reinterpret_cast<unsigned*>(&o2);
    out.w = *reinterpret_cast<unsigned*>(&o3);
    fn[node * 8 + sl] = out;
}

// ---------------------------------------------------------------------------
__global__ void final_kernel(const float4* __restrict__ x4,
                             float4* __restrict__ out4) {
    int i = blockIdx.x * blockDim.x + threadIdx.x;
    if (i >= NF4) return;
    float4 v = x4[i];
    float4 o;
    o.x = 0.6f * v.x; o.y = 0.6f * v.y; o.z = 0.6f * v.z; o.w = 0.6f * v.w;

    const float TH[5] = {0.6f, -0.4f, 0.3f, -0.2f, 0.1f};
#pragma unroll
    for (int k = 1; k <= 4; k++) {
        float2 f0 = __half22float2(g_feat[k][2 * i]);
        float2 f1 = __half22float2(g_feat[k][2 * i + 1]);
        o.x = fmaf(TH[k], f0.x, o.x);
        o.y = fmaf(TH[k], f0.y, o.y);
        o.z = fmaf(TH[k], f1.x, o.z);
        o.w = fmaf(TH[k], f1.y, o.w);
    }
    out4[i] = o;
}

// ---------------------------------------------------------------------------
extern "C" void kernel_launch(void* const* d_in, const int* in_sizes, int n_in,
                              void* d_out, int out_size) {
    const float4* x4 = (const float4*)d_in[0];
    const void*   ei = d_in[1];
    float4* out4 = (float4*)d_out;

    detect_idx_kernel<<<1, 32>>>((const int*)ei);
    zerodeg_kernel<<<NB, 256>>>();
    deg_kernel<<<(NEDGES + 255) / 256, 256>>>(ei);
    partial_kernel<<<NB, 256>>>();
    scanblock_kernel<<<1, 512>>>();
    offsets_kernel<<<NB, 256>>>();
    dis_kernel<<<NB, 256>>>();
    fill_kernel<<<(NEDGES + 255) / 256, 256>>>(ei);
    init_kernel<<<(NF4 + 255) / 256, 256>>>(x4);

    const int gthreads = NNODES * 8;
    for (int k = 1; k <= 4; k++)
        gather_kernel<<<(gthreads + 255) / 256, 256>>>(k);

    final_kernel<<<(NF4 + 255) / 256, 256>>>(x4, out4);
}